// round 1
// baseline (speedup 1.0000x reference)
#include <cuda_runtime.h>

#define N_NODES 20000
#define IN_DIM 256
#define HID 128
#define OUT_DIM 64
#define N_LAYERS 4
#define N_PATHS 8
#define PATH_LEN 8
#define N_TYPES 2

// -------- scratch (no allocations allowed; device globals) --------
__device__ float g_in_feats[N_NODES * HID];
__device__ float g_bufA[N_NODES * HID];
__device__ float g_bufB[N_NODES * HID];
__device__ float g_fout[N_NODES * N_TYPES * HID];

__device__ __forceinline__ float* buf_ptr(int s) {
    return s == 0 ? g_in_feats : (s == 1 ? g_bufA : g_bufB);
}

// ============================================================================
// Tiled SGEMM:  C[M, BN] = EPI( A[M, KDIM] @ W[BN, KDIM]^T )
//   EPI==0: relu(acc + bias[n])
//   EPI==1: 0.8*relu(acc) + 0.1*pre + 0.1*inf
// Block tile: 64 x BN, 256 threads, per-thread 4 x TN microtile.
// ============================================================================
template <int KDIM, int BN, int TN, int EPI>
__device__ __forceinline__ void gemm_body(
    const float* __restrict__ A, const float* __restrict__ W,
    const float* __restrict__ bias, const float* __restrict__ pre,
    const float* __restrict__ inf, float* __restrict__ C)
{
    constexpr int BM = 64, BK = 16, TM = 4;
    __shared__ float As[BK][BM];
    __shared__ float Bs[BK][BN];

    const int tid  = threadIdx.x;
    const int tcol = tid & 15;   // 16 thread-cols
    const int trow = tid >> 4;   // 16 thread-rows
    const int m0   = blockIdx.x * BM;

    float acc[TM][TN];
#pragma unroll
    for (int i = 0; i < TM; i++)
#pragma unroll
        for (int j = 0; j < TN; j++) acc[i][j] = 0.f;

    const int  am      = tid >> 2;          // 0..63
    const int  ak      = (tid & 3) << 2;    // 0,4,8,12
    const bool arow_ok = (m0 + am) < N_NODES;

    for (int k0 = 0; k0 < KDIM; k0 += BK) {
        // ---- load A tile (64x16), transposed into As[k][m] ----
        float4 va = make_float4(0.f, 0.f, 0.f, 0.f);
        if (arow_ok)
            va = *(const float4*)(A + (size_t)(m0 + am) * KDIM + k0 + ak);
        As[ak + 0][am] = va.x; As[ak + 1][am] = va.y;
        As[ak + 2][am] = va.z; As[ak + 3][am] = va.w;

        // ---- load W tile (BN x 16), transposed into Bs[k][n] ----
        if constexpr (BN == 128) {
            int bn = tid >> 1, bk = (tid & 1) << 3;
            float4 v0 = *(const float4*)(W + (size_t)bn * KDIM + k0 + bk);
            float4 v1 = *(const float4*)(W + (size_t)bn * KDIM + k0 + bk + 4);
            Bs[bk + 0][bn] = v0.x; Bs[bk + 1][bn] = v0.y;
            Bs[bk + 2][bn] = v0.z; Bs[bk + 3][bn] = v0.w;
            Bs[bk + 4][bn] = v1.x; Bs[bk + 5][bn] = v1.y;
            Bs[bk + 6][bn] = v1.z; Bs[bk + 7][bn] = v1.w;
        } else {  // BN == 64
            int bn = tid >> 2, bk = (tid & 3) << 2;
            float4 v0 = *(const float4*)(W + (size_t)bn * KDIM + k0 + bk);
            Bs[bk + 0][bn] = v0.x; Bs[bk + 1][bn] = v0.y;
            Bs[bk + 2][bn] = v0.z; Bs[bk + 3][bn] = v0.w;
        }
        __syncthreads();

#pragma unroll
        for (int k = 0; k < BK; k++) {
            float a[TM], b[TN];
#pragma unroll
            for (int i = 0; i < TM; i++) a[i] = As[k][trow * TM + i];
#pragma unroll
            for (int j = 0; j < TN; j++) b[j] = Bs[k][tcol * TN + j];
#pragma unroll
            for (int i = 0; i < TM; i++)
#pragma unroll
                for (int j = 0; j < TN; j++)
                    acc[i][j] = fmaf(a[i], b[j], acc[i][j]);
        }
        __syncthreads();
    }

    // ---- epilogue ----
#pragma unroll
    for (int i = 0; i < TM; i++) {
        int m = m0 + trow * TM + i;
        if (m >= N_NODES) continue;
#pragma unroll
        for (int j = 0; j < TN; j++) {
            int n = tcol * TN + j;
            float v = acc[i][j];
            size_t off = (size_t)m * BN + n;
            if constexpr (EPI == 0) {
                v += bias[n];
                v = v > 0.f ? v : 0.f;
            } else {
                v = v > 0.f ? v : 0.f;
                v = 0.8f * v + 0.1f * pre[off] + 0.1f * inf[off];
            }
            C[off] = v;
        }
    }
}

__global__ void __launch_bounds__(256)
fc_in_kernel(const float* __restrict__ x, const float* __restrict__ w,
             const float* __restrict__ b)
{
    gemm_body<IN_DIM, HID, 8, 0>(x, w, b, nullptr, nullptr, g_in_feats);
}

__global__ void __launch_bounds__(256)
layer_gemm_kernel(const float* __restrict__ w, int pre_sel, int out_sel)
{
    gemm_body<N_TYPES * HID, HID, 8, 1>(g_fout, w, nullptr,
                                        buf_ptr(pre_sel), g_in_feats,
                                        buf_ptr(out_sel));
}

__global__ void __launch_bounds__(256)
fc_out_kernel(const float* __restrict__ w, const float* __restrict__ b,
              float* __restrict__ out, int feats_sel)
{
    gemm_body<HID, OUT_DIM, 4, 0>(buf_ptr(feats_sel), w, b, nullptr, nullptr, out);
}

// ============================================================================
// Gather + per-type mean:
//   fout[n, t*128 + h] = mean_{p: type(p)==t} sum_l feats[paths[p,n,l], h] * pw[t,l,h]
// 2 nodes per 256-thread block; thread h of a node covers one feature lane.
// All gathered rows are 512B contiguous -> fully coalesced L2 reads.
// ============================================================================
__global__ void __launch_bounds__(256)
gather_kernel(const int* __restrict__ paths, const int* __restrict__ ptypes,
              const float* __restrict__ pw, int feats_sel)
{
    const float* __restrict__ feats = buf_ptr(feats_sel);
    __shared__ int idx_s[2][N_PATHS * PATH_LEN];
    __shared__ int types_s[N_PATHS];

    const int tid  = threadIdx.x;
    const int slot = tid >> 7;       // 0,1
    const int h    = tid & 127;
    const int n    = blockIdx.x * 2 + slot;

    if (tid < N_PATHS) types_s[tid] = ptypes[tid];
    if (h < N_PATHS * PATH_LEN) {
        int p = h >> 3, l = h & 7;
        idx_s[slot][h] = paths[p * (N_NODES * PATH_LEN) + n * PATH_LEN + l];
    }
    __syncthreads();

    // per-type path weights for this feature lane
    float w0[PATH_LEN], w1[PATH_LEN];
#pragma unroll
    for (int l = 0; l < PATH_LEN; l++) {
        w0[l] = pw[l * HID + h];
        w1[l] = pw[PATH_LEN * HID + l * HID + h];
    }

    float acc0 = 0.f, acc1 = 0.f;
    int c0 = 0, c1 = 0;
#pragma unroll
    for (int p = 0; p < N_PATHS; p++) {
        const int t = types_s[p];
        float a = 0.f;
#pragma unroll
        for (int l = 0; l < PATH_LEN; l++) {
            float f = __ldg(feats + (size_t)idx_s[slot][p * PATH_LEN + l] * HID + h);
            float w = t ? w1[l] : w0[l];
            a = fmaf(f, w, a);
        }
        if (t) { acc1 += a; c1++; } else { acc0 += a; c0++; }
    }

    float* fo = g_fout + (size_t)n * (N_TYPES * HID);
    fo[h]       = acc0 * (1.0f / (float)c0);
    fo[HID + h] = acc1 * (1.0f / (float)c1);
}

// ============================================================================
extern "C" void kernel_launch(void* const* d_in, const int* in_sizes, int n_in,
                              void* d_out, int out_size)
{
    const float* input_x    = (const float*)d_in[0];
    const int*   paths      = (const int*)d_in[1];
    const int*   ptypes     = (const int*)d_in[2];
    const float* fc_in_w    = (const float*)d_in[3];
    const float* fc_in_b    = (const float*)d_in[4];
    const float* fc_out_w   = (const float*)d_in[5];
    const float* fc_out_b   = (const float*)d_in[6];
    const float* layer_fc_w = (const float*)d_in[7];
    const float* path_w     = (const float*)d_in[8];
    float* out = (float*)d_out;

    const dim3 blk(256);
    const dim3 ggrd((N_NODES + 63) / 64);

    fc_in_kernel<<<ggrd, blk>>>(input_x, fc_in_w, fc_in_b);

    int cur = 0;  // feats = g_in_feats
    for (int i = 0; i < N_LAYERS; i++) {
        gather_kernel<<<N_NODES / 2, blk>>>(
            paths, ptypes, path_w + (size_t)i * N_TYPES * PATH_LEN * HID, cur);
        int nxt = (cur == 1) ? 2 : 1;
        layer_gemm_kernel<<<ggrd, blk>>>(
            layer_fc_w + (size_t)i * HID * (N_TYPES * HID), cur, nxt);
        cur = nxt;
    }

    fc_out_kernel<<<ggrd, blk>>>(fc_out_w, fc_out_b, out, cur);
}

// round 2
// speedup vs baseline: 1.2418x; 1.2418x over previous
#include <cuda_runtime.h>

#define N_NODES 20000
#define IN_DIM 256
#define HID 128
#define OUT_DIM 64
#define N_LAYERS 4
#define N_PATHS 8
#define PATH_LEN 8
#define N_TYPES 2

// -------- scratch (no allocations allowed; device globals) --------
__device__ float g_in_feats[N_NODES * HID];
__device__ float g_bufA[N_NODES * HID];
__device__ float g_bufB[N_NODES * HID];
__device__ float g_fout[N_NODES * N_TYPES * HID];

__device__ __forceinline__ float* buf_ptr(int s) {
    return s == 0 ? g_in_feats : (s == 1 ? g_bufA : g_bufB);
}

// ============================================================================
// Tiled SGEMM:  C[M, BN] = EPI( A[M, KDIM] @ W[BN, KDIM]^T )
//   EPI==0: relu(acc + bias[n])
//   EPI==1: 0.8*relu(acc) + 0.1*pre + 0.1*inf
// Block tile: 128 x BN, 256 threads, per-thread 8 x TN microtile,
// float4 shared-memory loads in the inner loop.
// ============================================================================
template <int KDIM, int BN, int TN, int EPI>
__device__ __forceinline__ void gemm_body(
    const float* __restrict__ A, const float* __restrict__ W,
    const float* __restrict__ bias, const float* __restrict__ pre,
    const float* __restrict__ inf, float* __restrict__ C)
{
    constexpr int BM = 128, BK = 16, TM = 8;
    __shared__ float As[BK][BM];
    __shared__ float Bs[BK][BN];

    const int tid  = threadIdx.x;
    const int tcol = tid % (BN / TN);   // 16 thread-cols
    const int trow = tid / (BN / TN);   // 16 thread-rows
    const int m0   = blockIdx.x * BM;

    float acc[TM][TN];
#pragma unroll
    for (int i = 0; i < TM; i++)
#pragma unroll
        for (int j = 0; j < TN; j++) acc[i][j] = 0.f;

    // A-tile loader mapping: each thread loads 8 consecutive k of one row
    const int  am      = tid >> 1;        // 0..127
    const int  ak      = (tid & 1) << 3;  // 0 or 8
    const bool arow_ok = (m0 + am) < N_NODES;
    const float* Arow  = A + (size_t)(m0 + am) * KDIM + ak;

    for (int k0 = 0; k0 < KDIM; k0 += BK) {
        // ---- A tile (128x16) -> As[k][m] ----
        float4 va0 = make_float4(0.f, 0.f, 0.f, 0.f);
        float4 va1 = make_float4(0.f, 0.f, 0.f, 0.f);
        if (arow_ok) {
            va0 = *(const float4*)(Arow + k0);
            va1 = *(const float4*)(Arow + k0 + 4);
        }
        As[ak + 0][am] = va0.x; As[ak + 1][am] = va0.y;
        As[ak + 2][am] = va0.z; As[ak + 3][am] = va0.w;
        As[ak + 4][am] = va1.x; As[ak + 5][am] = va1.y;
        As[ak + 6][am] = va1.z; As[ak + 7][am] = va1.w;

        // ---- W tile (BN x 16) -> Bs[k][n] ----
        if constexpr (BN == 128) {
            int bn = tid >> 1, bk = (tid & 1) << 3;
            float4 v0 = *(const float4*)(W + (size_t)bn * KDIM + k0 + bk);
            float4 v1 = *(const float4*)(W + (size_t)bn * KDIM + k0 + bk + 4);
            Bs[bk + 0][bn] = v0.x; Bs[bk + 1][bn] = v0.y;
            Bs[bk + 2][bn] = v0.z; Bs[bk + 3][bn] = v0.w;
            Bs[bk + 4][bn] = v1.x; Bs[bk + 5][bn] = v1.y;
            Bs[bk + 6][bn] = v1.z; Bs[bk + 7][bn] = v1.w;
        } else {  // BN == 64
            int bn = tid >> 2, bk = (tid & 3) << 2;
            float4 v0 = *(const float4*)(W + (size_t)bn * KDIM + k0 + bk);
            Bs[bk + 0][bn] = v0.x; Bs[bk + 1][bn] = v0.y;
            Bs[bk + 2][bn] = v0.z; Bs[bk + 3][bn] = v0.w;
        }
        __syncthreads();

#pragma unroll
        for (int k = 0; k < BK; k++) {
            float a[TM], b[TN];
            *(float4*)&a[0] = *(const float4*)&As[k][trow * TM];
            *(float4*)&a[4] = *(const float4*)&As[k][trow * TM + 4];
            *(float4*)&b[0] = *(const float4*)&Bs[k][tcol * TN];
            if constexpr (TN == 8)
                *(float4*)&b[4] = *(const float4*)&Bs[k][tcol * TN + 4];
#pragma unroll
            for (int i = 0; i < TM; i++)
#pragma unroll
                for (int j = 0; j < TN; j++)
                    acc[i][j] = fmaf(a[i], b[j], acc[i][j]);
        }
        __syncthreads();
    }

    // ---- epilogue (float4 stores) ----
#pragma unroll
    for (int i = 0; i < TM; i++) {
        int m = m0 + trow * TM + i;
        if (m >= N_NODES) continue;
        size_t rowoff = (size_t)m * BN + tcol * TN;
#pragma unroll
        for (int j = 0; j < TN; j += 4) {
            float4 v;
            v.x = acc[i][j + 0]; v.y = acc[i][j + 1];
            v.z = acc[i][j + 2]; v.w = acc[i][j + 3];
            if constexpr (EPI == 0) {
                int n = tcol * TN + j;
                v.x += bias[n + 0]; v.y += bias[n + 1];
                v.z += bias[n + 2]; v.w += bias[n + 3];
                v.x = fmaxf(v.x, 0.f); v.y = fmaxf(v.y, 0.f);
                v.z = fmaxf(v.z, 0.f); v.w = fmaxf(v.w, 0.f);
            } else {
                float4 p4 = *(const float4*)(pre + rowoff + j);
                float4 f4 = *(const float4*)(inf + rowoff + j);
                v.x = 0.8f * fmaxf(v.x, 0.f) + 0.1f * p4.x + 0.1f * f4.x;
                v.y = 0.8f * fmaxf(v.y, 0.f) + 0.1f * p4.y + 0.1f * f4.y;
                v.z = 0.8f * fmaxf(v.z, 0.f) + 0.1f * p4.z + 0.1f * f4.z;
                v.w = 0.8f * fmaxf(v.w, 0.f) + 0.1f * p4.w + 0.1f * f4.w;
            }
            *(float4*)(C + rowoff + j) = v;
        }
    }
}

__global__ void __launch_bounds__(256)
fc_in_kernel(const float* __restrict__ x, const float* __restrict__ w,
             const float* __restrict__ b)
{
    gemm_body<IN_DIM, HID, 8, 0>(x, w, b, nullptr, nullptr, g_in_feats);
}

__global__ void __launch_bounds__(256)
layer_gemm_kernel(const float* __restrict__ w, int pre_sel, int out_sel)
{
    gemm_body<N_TYPES * HID, HID, 8, 1>(g_fout, w, nullptr,
                                        buf_ptr(pre_sel), g_in_feats,
                                        buf_ptr(out_sel));
}

__global__ void __launch_bounds__(256)
fc_out_kernel(const float* __restrict__ w, const float* __restrict__ b,
              float* __restrict__ out, int feats_sel)
{
    gemm_body<HID, OUT_DIM, 4, 0>(buf_ptr(feats_sel), w, b, nullptr, nullptr, out);
}

// ============================================================================
// Gather + per-type mean (float2-vectorized):
//   fout[n, t*128 + h] = mean_{p: type(p)==t} sum_l feats[paths[p,n,l], h] * pw[t,l,h]
// 4 nodes per 256-thread block; 64 threads per node, each handling 2 lanes.
// ============================================================================
__global__ void __launch_bounds__(256)
gather_kernel(const int* __restrict__ paths, const int* __restrict__ ptypes,
              const float* __restrict__ pw, int feats_sel)
{
    const float2* __restrict__ feats2 = (const float2*)buf_ptr(feats_sel);
    const float2* __restrict__ pw2    = (const float2*)pw;

    __shared__ int idx_s[4][N_PATHS * PATH_LEN];
    __shared__ int types_s[N_PATHS];

    const int tid  = threadIdx.x;
    const int slot = tid >> 6;       // 0..3
    const int hh   = tid & 63;       // float2 lane (h = 2*hh)
    const int n    = blockIdx.x * 4 + slot;

    if (tid < N_PATHS) types_s[tid] = ptypes[tid];
    {
        int p = hh >> 3, l = hh & 7;
        idx_s[slot][hh] = paths[p * (N_NODES * PATH_LEN) + n * PATH_LEN + l];
    }
    __syncthreads();

    // per-type path weights for these two feature lanes
    float2 w0[PATH_LEN], w1[PATH_LEN];
#pragma unroll
    for (int l = 0; l < PATH_LEN; l++) {
        w0[l] = pw2[l * (HID / 2) + hh];
        w1[l] = pw2[PATH_LEN * (HID / 2) + l * (HID / 2) + hh];
    }

    float2 acc0 = make_float2(0.f, 0.f), acc1 = make_float2(0.f, 0.f);
    int c0 = 0, c1 = 0;
#pragma unroll
    for (int p = 0; p < N_PATHS; p++) {
        const int t = types_s[p];
        float2 a = make_float2(0.f, 0.f);
#pragma unroll
        for (int l = 0; l < PATH_LEN; l++) {
            float2 f = __ldg(feats2 +
                (size_t)idx_s[slot][p * PATH_LEN + l] * (HID / 2) + hh);
            float2 w = t ? w1[l] : w0[l];
            a.x = fmaf(f.x, w.x, a.x);
            a.y = fmaf(f.y, w.y, a.y);
        }
        if (t) { acc1.x += a.x; acc1.y += a.y; c1++; }
        else   { acc0.x += a.x; acc0.y += a.y; c0++; }
    }

    float inv0 = 1.0f / (float)c0, inv1 = 1.0f / (float)c1;
    float2* fo2 = (float2*)(g_fout + (size_t)n * (N_TYPES * HID));
    fo2[hh]            = make_float2(acc0.x * inv0, acc0.y * inv0);
    fo2[HID / 2 + hh]  = make_float2(acc1.x * inv1, acc1.y * inv1);
}

// ============================================================================
extern "C" void kernel_launch(void* const* d_in, const int* in_sizes, int n_in,
                              void* d_out, int out_size)
{
    const float* input_x    = (const float*)d_in[0];
    const int*   paths      = (const int*)d_in[1];
    const int*   ptypes     = (const int*)d_in[2];
    const float* fc_in_w    = (const float*)d_in[3];
    const float* fc_in_b    = (const float*)d_in[4];
    const float* fc_out_w   = (const float*)d_in[5];
    const float* fc_out_b   = (const float*)d_in[6];
    const float* layer_fc_w = (const float*)d_in[7];
    const float* path_w     = (const float*)d_in[8];
    float* out = (float*)d_out;

    const dim3 blk(256);
    const dim3 ggrd((N_NODES + 127) / 128);

    fc_in_kernel<<<ggrd, blk>>>(input_x, fc_in_w, fc_in_b);

    int cur = 0;  // feats = g_in_feats
    for (int i = 0; i < N_LAYERS; i++) {
        gather_kernel<<<N_NODES / 4, blk>>>(
            paths, ptypes, path_w + (size_t)i * N_TYPES * PATH_LEN * HID, cur);
        int nxt = (cur == 1) ? 2 : 1;
        layer_gemm_kernel<<<ggrd, blk>>>(
            layer_fc_w + (size_t)i * HID * (N_TYPES * HID), cur, nxt);
        cur = nxt;
    }

    fc_out_kernel<<<ggrd, blk>>>(fc_out_w, fc_out_b, out, cur);
}